// round 1
// baseline (speedup 1.0000x reference)
#include <cuda_runtime.h>
#include <math.h>

#define CDIV(a,b) (((a)+(b)-1)/(b))

// ---------------- problem dims ----------------
constexpr int kBS = 16, kN = 64;
constexpr int kB1 = kBS * kN;              // 1024 sequences
constexpr int kTC = 72, kBP = kBS * kTC;   // 1152 graph batches

// conv stage dims
// s1: cin 64,  lin 256, cout 256, pad 1 -> lout 256, pool 129
// s2: cin 256, lin 129, cout 128, pad 2 -> lout 131, pool 66
// s3: cin 128, lin 66,  cout 256, pad 3 -> lout 70,  pool 36

// ---------------- scratch ----------------
__device__ float g_t0[(size_t)kB1 * 64 * 256];
__device__ float g_c1[(size_t)kB1 * 256 * 256];
__device__ float g_p1[(size_t)kB1 * 256 * 129];
__device__ float g_c2[(size_t)kB1 * 128 * 131];
__device__ float g_p2[(size_t)kB1 * 128 * 66];
__device__ float g_c3[(size_t)kB1 * 256 * 70];
__device__ float g_p3[(size_t)kB1 * 256 * 36];
__device__ float g_nf[(size_t)kBP * 64 * 128];
__device__ float g_oo[(size_t)kBP * 64 * 64];
__device__ float g_mean[256];
__device__ float g_istd[256];

// ---------------- transpose: x[b,s,n,d] -> t0[b*64+n, d, s] ----------------
__global__ void transpose_k(const float* __restrict__ x, float* __restrict__ t0) {
    __shared__ float tile[32][33];
    int bn = blockIdx.x;
    int b = bn >> 6, n = bn & 63;
    int s0 = blockIdx.y * 32;
    int d0 = blockIdx.z * 32;
    int tx = threadIdx.x, ty = threadIdx.y;
#pragma unroll
    for (int r = 0; r < 4; r++) {
        int si = ty + r * 8;
        tile[si][tx] = x[(((size_t)(b * 256 + s0 + si)) * 64 + n) * 64 + d0 + tx];
    }
    __syncthreads();
#pragma unroll
    for (int r = 0; r < 4; r++) {
        int di = ty + r * 8;
        t0[((size_t)bn * 64 + d0 + di) * 256 + s0 + tx] = tile[tx][di];
    }
}

// ---------------- conv1d (cross-correlation, K=3) ----------------
// 64(cout) x 64(l) tile per block, 16x16 threads, 4x4 register micro-tile.
template <int CIN, int LIN, int COUT, int LOUT, int PAD>
__global__ void conv_k(const float* __restrict__ X, const float* __restrict__ W,
                       float* __restrict__ Y) {
    constexpr int CT = 32;
    __shared__ float Ws[64 * CT * 3];   // [co][cc][k]
    __shared__ float Xs[CT * 66];       // [cc][u], u relative to l0-PAD
    int bn = blockIdx.x;
    int co0 = blockIdx.y * 64;
    int l0 = blockIdx.z * 64;
    const float* Xb = X + (size_t)bn * CIN * LIN;
    int tx = threadIdx.x, ty = threadIdx.y;
    int tid = ty * 16 + tx;
    float acc[4][4] = {};
    for (int ci0 = 0; ci0 < CIN; ci0 += CT) {
        __syncthreads();
#pragma unroll 4
        for (int i = tid; i < 64 * CT * 3; i += 256) {
            int co = i / (CT * 3);
            int rem = i - co * (CT * 3);       // cc*3 + k
            Ws[i] = W[(size_t)(co0 + co) * CIN * 3 + ci0 * 3 + rem];
        }
        int base = l0 - PAD;
#pragma unroll 4
        for (int i = tid; i < CT * 66; i += 256) {
            int cc = i / 66;
            int u = i - cc * 66;
            int l = base + u;
            Xs[i] = (l >= 0 && l < LIN) ? Xb[(size_t)(ci0 + cc) * LIN + l] : 0.f;
        }
        __syncthreads();
#pragma unroll 4
        for (int cc = 0; cc < CT; cc++) {
            float xr[6];
#pragma unroll
            for (int j = 0; j < 6; j++) xr[j] = Xs[cc * 66 + tx * 4 + j];
#pragma unroll
            for (int k = 0; k < 3; k++) {
                float wr[4];
#pragma unroll
                for (int i = 0; i < 4; i++) wr[i] = Ws[(ty * 4 + i) * (CT * 3) + cc * 3 + k];
#pragma unroll
                for (int i = 0; i < 4; i++)
#pragma unroll
                    for (int j = 0; j < 4; j++)
                        acc[i][j] = fmaf(wr[i], xr[j + k], acc[i][j]);
            }
        }
    }
#pragma unroll
    for (int i = 0; i < 4; i++) {
        int co = co0 + ty * 4 + i;
#pragma unroll
        for (int j = 0; j < 4; j++) {
            int l = l0 + tx * 4 + j;
            if (l < LOUT) Y[((size_t)bn * COUT + co) * LOUT + l] = acc[i][j];
        }
    }
}

// ---------------- BN stats over (batch, length) for [B][C][L] ----------------
__global__ void stats_mid_k(const float* __restrict__ X, int B, int C, int L,
                            float* __restrict__ mean, float* __restrict__ istd) {
    int c = blockIdx.x, tid = threadIdx.x;
    int total = B * L;
    double s = 0.0, q = 0.0;
    for (int i = tid; i < total; i += 256) {
        int bI = i / L;
        int l = i - bI * L;
        float v = X[((size_t)bI * C + c) * L + l];
        s += v;
        q += (double)v * v;
    }
    __shared__ double ss[256], qs[256];
    ss[tid] = s; qs[tid] = q;
    __syncthreads();
    for (int o = 128; o > 0; o >>= 1) {
        if (tid < o) { ss[tid] += ss[tid + o]; qs[tid] += qs[tid + o]; }
        __syncthreads();
    }
    if (tid == 0) {
        double m = ss[0] / total;
        double var = qs[0] / total - m * m;
        mean[c] = (float)m;
        istd[c] = rsqrtf((float)var + 1e-5f);
    }
}

// ---------------- BN stats over rows for [M][C] (channel-last) ----------------
__global__ void stats_last_k(const float* __restrict__ X, int M, int C,
                             float* __restrict__ mean, float* __restrict__ istd) {
    int c = blockIdx.x, tid = threadIdx.x;
    double s = 0.0, q = 0.0;
    for (int i = tid; i < M; i += 256) {
        float v = X[(size_t)i * C + c];
        s += v;
        q += (double)v * v;
    }
    __shared__ double ss[256], qs[256];
    ss[tid] = s; qs[tid] = q;
    __syncthreads();
    for (int o = 128; o > 0; o >>= 1) {
        if (tid < o) { ss[tid] += ss[tid + o]; qs[tid] += qs[tid + o]; }
        __syncthreads();
    }
    if (tid == 0) {
        double m = ss[0] / M;
        double var = qs[0] / M - m * m;
        mean[c] = (float)m;
        istd[c] = rsqrtf((float)var + 1e-5f);
    }
}

// ---------------- fused BN + ReLU + maxpool(k=2,s=2,p=1) ----------------
__global__ void bnpool_k(const float* __restrict__ X, float* __restrict__ Y,
                         const float* __restrict__ mean, const float* __restrict__ istd,
                         const float* __restrict__ gam, const float* __restrict__ bet,
                         int C, int Lout, int Lp) {
    int idx = blockIdx.x * 256 + threadIdx.x;
    int total = kB1 * C * Lp;
    if (idx >= total) return;
    int j = idx % Lp;
    int c = (idx / Lp) % C;
    int bn = idx / (Lp * C);
    float sc = istd[c] * gam[c];
    float sh = bet[c] - mean[c] * sc;
    const float* row = X + ((size_t)bn * C + c) * Lout;
    float m = 0.f;  // relu floor; at least one window element always valid
    int l0 = 2 * j - 1, l1 = 2 * j;
    if (l0 >= 0 && l0 < Lout) { float v = fmaf(row[l0], sc, sh); if (v > m) m = v; }
    if (l1 < Lout)            { float v = fmaf(row[l1], sc, sh); if (v > m) m = v; }
    Y[idx] = m;
}

// ---------------- nf = spa @ map_w.T + map_b ----------------
// spa[bp][n][f] = p3_flat[(b*64+n)*9216 + tc*128 + f]  (contiguous 128 floats)
__global__ void nf_k(const float* __restrict__ P3, const float* __restrict__ MW,
                     const float* __restrict__ MB, float* __restrict__ NF) {
    extern __shared__ float sm[];
    float* As = sm;            // [64][129]
    float* Bs = sm + 64 * 129; // [64][129]
    int bp = blockIdx.x;
    int fo0 = blockIdx.y * 64;
    int b = bp / kTC, tc = bp % kTC;
    int tx = threadIdx.x, ty = threadIdx.y;
    int tid = ty * 16 + tx;
    for (int i = tid; i < 64 * 128; i += 256) {
        int r = i >> 7, f = i & 127;
        As[r * 129 + f] = P3[(size_t)(b * kN + r) * 9216 + tc * 128 + f];
        Bs[r * 129 + f] = MW[(size_t)(fo0 + r) * 128 + f];
    }
    __syncthreads();
    float acc[4][4] = {};
#pragma unroll 4
    for (int f = 0; f < 128; f++) {
        float ar[4], br[4];
#pragma unroll
        for (int i = 0; i < 4; i++) ar[i] = As[(ty * 4 + i) * 129 + f];
#pragma unroll
        for (int j = 0; j < 4; j++) br[j] = Bs[(tx * 4 + j) * 129 + f];
#pragma unroll
        for (int i = 0; i < 4; i++)
#pragma unroll
            for (int j = 0; j < 4; j++) acc[i][j] = fmaf(ar[i], br[j], acc[i][j]);
    }
#pragma unroll
    for (int i = 0; i < 4; i++)
#pragma unroll
        for (int j = 0; j < 4; j++)
            NF[((size_t)bp * 64 + ty * 4 + i) * 128 + fo0 + tx * 4 + j] =
                acc[i][j] + MB[fo0 + tx * 4 + j];
}

// ---------------- graph kernel: adj + softmax + aggregate + theta ----------------
__global__ void adj_k(const float* __restrict__ NF, const float* __restrict__ TW,
                      const float* __restrict__ TB, float* __restrict__ OUT) {
    extern __shared__ float sm[];
    float* nfs = sm;                 // [64][129]
    float* ths = nfs + 64 * 129;     // [64][129]
    float* A   = ths + 64 * 129;     // [64][66]
    float* M2  = A + 64 * 66;        // [64][66]
    int bp = blockIdx.x;
    int tx = threadIdx.x, ty = threadIdx.y;
    int tid = ty * 16 + tx;
    for (int i = tid; i < 64 * 128; i += 256) {
        int r = i >> 7, f = i & 127;
        nfs[r * 129 + f] = NF[(size_t)bp * 8192 + i];
        ths[r * 129 + f] = TW[i];
    }
    __syncthreads();
    {
        float a1[4][4] = {}, a2[4][4] = {};
#pragma unroll 4
        for (int f = 0; f < 128; f++) {
            float ar[4], b1[4], b2[4];
#pragma unroll
            for (int i = 0; i < 4; i++) ar[i] = nfs[(ty * 4 + i) * 129 + f];
#pragma unroll
            for (int j = 0; j < 4; j++) b1[j] = nfs[(tx * 4 + j) * 129 + f];
#pragma unroll
            for (int j = 0; j < 4; j++) b2[j] = ths[(tx * 4 + j) * 129 + f];
#pragma unroll
            for (int i = 0; i < 4; i++)
#pragma unroll
                for (int j = 0; j < 4; j++) {
                    a1[i][j] = fmaf(ar[i], b1[j], a1[i][j]);
                    a2[i][j] = fmaf(ar[i], b2[j], a2[i][j]);
                }
        }
#pragma unroll
        for (int i = 0; i < 4; i++)
#pragma unroll
            for (int j = 0; j < 4; j++) {
                A[(ty * 4 + i) * 66 + tx * 4 + j] = a1[i][j];
                M2[(ty * 4 + i) * 66 + tx * 4 + j] = a2[i][j];
            }
    }
    __syncthreads();
    {   // softmax rows: 4 lanes per row, 16 cols each
        int row = tid >> 2;
        int part = tid & 3;
        float vals[16];
        float mx = -3.4e38f;
#pragma unroll
        for (int jj = 0; jj < 16; jj++) {
            int col = part * 16 + jj;
            float v = A[row * 66 + col];
            if (col == row) v -= 1e8f;
            v = v > 0.f ? v : 0.01f * v;   // leaky_relu
            vals[jj] = v;
            mx = fmaxf(mx, v);
        }
        mx = fmaxf(mx, __shfl_xor_sync(0xFFFFFFFFu, mx, 1));
        mx = fmaxf(mx, __shfl_xor_sync(0xFFFFFFFFu, mx, 2));
        float s = 0.f;
#pragma unroll
        for (int jj = 0; jj < 16; jj++) { vals[jj] = expf(vals[jj] - mx); s += vals[jj]; }
        s += __shfl_xor_sync(0xFFFFFFFFu, s, 1);
        s += __shfl_xor_sync(0xFFFFFFFFu, s, 2);
        float inv = 1.f / s;
#pragma unroll
        for (int jj = 0; jj < 16; jj++) {
            int col = part * 16 + jj;
            float r2 = vals[jj] * inv;
            if (col == row) r2 += 1.f;     // + eye
            A[row * 66 + col] = r2;
        }
    }
    __syncthreads();
    {
        float acc[4][4] = {};
#pragma unroll 4
        for (int j = 0; j < 64; j++) {
            float ar[4], br[4];
#pragma unroll
            for (int i = 0; i < 4; i++) ar[i] = A[(ty * 4 + i) * 66 + j];
#pragma unroll
            for (int jo = 0; jo < 4; jo++) br[jo] = M2[j * 66 + tx * 4 + jo];
#pragma unroll
            for (int i = 0; i < 4; i++)
#pragma unroll
                for (int jo = 0; jo < 4; jo++) acc[i][jo] = fmaf(ar[i], br[jo], acc[i][jo]);
        }
#pragma unroll
        for (int i = 0; i < 4; i++)
#pragma unroll
            for (int jo = 0; jo < 4; jo++)
                OUT[((size_t)bp * 64 + ty * 4 + i) * 64 + tx * 4 + jo] =
                    acc[i][jo] + TB[tx * 4 + jo];
    }
}

// ---------------- final: BN + leaky + pair-mean ----------------
__global__ void final_k(const float* __restrict__ Xo,
                        const float* __restrict__ mean, const float* __restrict__ istd,
                        const float* __restrict__ gam, const float* __restrict__ bet,
                        float* __restrict__ Y) {
    int idx = blockIdx.x * 256 + threadIdx.x;
    if (idx >= kBS * 36 * 64 * 64) return;
    int o = idx & 63;
    int n = (idx >> 6) & 63;
    int w = (idx >> 12) % 36;
    int b = idx / (36 * 4096);
    float sc = istd[o] * gam[o];
    float sh = bet[o] - mean[o] * sc;
    float acc = 0.f;
#pragma unroll
    for (int e = 0; e < 2; e++) {
        float v = fmaf(Xo[(((size_t)(b * kTC + 2 * w + e)) * 64 + n) * 64 + o], sc, sh);
        acc += (v > 0.f ? v : 0.01f * v);
    }
    Y[idx] = 0.5f * acc;
}

// ---------------- launch ----------------
extern "C" void kernel_launch(void* const* d_in, const int* in_sizes, int n_in,
                              void* d_out, int out_size) {
    const float* x   = (const float*)d_in[0];
    const float* w1  = (const float*)d_in[1];
    const float* g1  = (const float*)d_in[2];
    const float* b1  = (const float*)d_in[3];
    const float* w2  = (const float*)d_in[4];
    const float* g2  = (const float*)d_in[5];
    const float* b2  = (const float*)d_in[6];
    const float* w3  = (const float*)d_in[7];
    const float* g3  = (const float*)d_in[8];
    const float* b3  = (const float*)d_in[9];
    const float* mw  = (const float*)d_in[10];
    const float* mb  = (const float*)d_in[11];
    const float* tw  = (const float*)d_in[12];
    const float* tbv = (const float*)d_in[13];
    const float* bg  = (const float*)d_in[14];
    const float* bb  = (const float*)d_in[15];
    float* out = (float*)d_out;

    float *t0, *c1, *p1, *c2, *p2, *c3, *p3, *nf, *oo, *mn, *is;
    cudaGetSymbolAddress((void**)&t0, g_t0);
    cudaGetSymbolAddress((void**)&c1, g_c1);
    cudaGetSymbolAddress((void**)&p1, g_p1);
    cudaGetSymbolAddress((void**)&c2, g_c2);
    cudaGetSymbolAddress((void**)&p2, g_p2);
    cudaGetSymbolAddress((void**)&c3, g_c3);
    cudaGetSymbolAddress((void**)&p3, g_p3);
    cudaGetSymbolAddress((void**)&nf, g_nf);
    cudaGetSymbolAddress((void**)&oo, g_oo);
    cudaGetSymbolAddress((void**)&mn, g_mean);
    cudaGetSymbolAddress((void**)&is, g_istd);

    const int NF_SMEM = 2 * 64 * 129 * 4;                        // 66048 B
    const int ADJ_SMEM = (2 * 64 * 129 + 2 * 64 * 66) * 4;       // 99840 B
    cudaFuncSetAttribute(nf_k, cudaFuncAttributeMaxDynamicSharedMemorySize, NF_SMEM);
    cudaFuncSetAttribute(adj_k, cudaFuncAttributeMaxDynamicSharedMemorySize, ADJ_SMEM);

    dim3 thr(16, 16);

    transpose_k<<<dim3(kB1, 8, 2), dim3(32, 8)>>>(x, t0);

    // stage 1
    conv_k<64, 256, 256, 256, 1><<<dim3(kB1, 4, 4), thr>>>(t0, w1, c1);
    stats_mid_k<<<256, 256>>>(c1, kB1, 256, 256, mn, is);
    bnpool_k<<<CDIV(kB1 * 256 * 129, 256), 256>>>(c1, p1, mn, is, g1, b1, 256, 256, 129);

    // stage 2
    conv_k<256, 129, 128, 131, 2><<<dim3(kB1, 2, 3), thr>>>(p1, w2, c2);
    stats_mid_k<<<128, 256>>>(c2, kB1, 128, 131, mn, is);
    bnpool_k<<<CDIV(kB1 * 128 * 66, 256), 256>>>(c2, p2, mn, is, g2, b2, 128, 131, 66);

    // stage 3
    conv_k<128, 66, 256, 70, 3><<<dim3(kB1, 4, 2), thr>>>(p2, w3, c3);
    stats_mid_k<<<256, 256>>>(c3, kB1, 256, 70, mn, is);
    bnpool_k<<<CDIV(kB1 * 256 * 36, 256), 256>>>(c3, p3, mn, is, g3, b3, 256, 70, 36);

    // graph part
    nf_k<<<dim3(kBP, 2), thr, NF_SMEM>>>(p3, mw, mb, nf);
    adj_k<<<kBP, thr, ADJ_SMEM>>>(nf, tw, tbv, oo);
    stats_last_k<<<64, 256>>>(oo, kBP * 64, 64, mn, is);
    final_k<<<CDIV(kBS * 36 * 64 * 64, 256), 256>>>(oo, mn, is, bg, bb, out);
}